// round 1
// baseline (speedup 1.0000x reference)
#include <cuda_runtime.h>

#define B_  8
#define H_  8
#define QS_ 64
#define KS_ 512
#define A_  64
#define DH_ 64
#define KC_ 128
#define QD_ 512
#define KD_ 512

// 8 MB scratch for scores [B][H][QS][KS]
__device__ float g_scores[B_*H_*QS_*KS_];

__device__ __forceinline__ float fast_tanh(float v) {
    float y;
    asm("tanh.approx.f32 %0, %1;" : "=f"(y) : "f"(v));
    return y;
}

// ---------------- kernel 1: fused projections + tanh scores ----------------
// smem layout (floats):
//   s_qp    : 64*65  = 4160   @ 0
//   s_kpb   : 128*65 = 8320   @ 4160
//   s_stage : 128*68 = 8704   @ 12480   (query tile, then x chunk)
//   s_W     : 64*68  = 4352   @ 21184   (Wq, then Wk)
//   s_bias  : 64              @ 25536
//   s_w2    : 64              @ 25600
#define SM1_FLOATS 25664

__global__ void __launch_bounds__(256, 2) scores_kernel(
    const float* __restrict__ x, const float* __restrict__ query,
    const float* __restrict__ W, const float* __restrict__ bias,
    const float* __restrict__ w2)
{
    extern __shared__ float sm[];
    float* s_qp    = sm;
    float* s_kpb   = sm + 4160;
    float* s_stage = sm + 12480;
    float* s_W     = sm + 21184;
    float* s_bias  = sm + 25536;
    float* s_w2    = sm + 25600;

    const int kc = blockIdx.x, h = blockIdx.y, b = blockIdx.z;
    const int tid = threadIdx.x;
    const int tx = tid & 15, ty = tid >> 4;

    if (tid < 64) { s_bias[tid] = bias[tid]; s_w2[tid] = w2[tid]; }

    // ---- load query tile [64][64] and Wq [64][64] ----
#pragma unroll
    for (int i = 0; i < 4; i++) {
        int idx = tid + 256 * i; int q = idx >> 4, d4 = idx & 15;
        *(float4*)&s_stage[q * 68 + d4 * 4] =
            *(const float4*)&query[(size_t)(b * QS_ + q) * QD_ + h * DH_ + d4 * 4];
    }
#pragma unroll
    for (int i = 0; i < 4; i++) {
        int idx = tid + 256 * i; int a = idx >> 4, d4 = idx & 15;
        *(float4*)&s_W[a * 68 + d4 * 4] =
            *(const float4*)&W[a * 128 + 64 + d4 * 4];
    }
    __syncthreads();

    // ---- qp[q][a] = sum_d qh[q][d]*Wq[a][d] + bias[a]   (a interleaved: a = tx + 16j)
    {
        float acc[4][4];
#pragma unroll
        for (int j = 0; j < 4; j++) {
            float bv = s_bias[tx + 16 * j];
#pragma unroll
            for (int i = 0; i < 4; i++) acc[i][j] = bv;
        }
#pragma unroll
        for (int d4 = 0; d4 < 16; d4++) {
            float4 qv[4], wv[4];
#pragma unroll
            for (int i = 0; i < 4; i++) qv[i] = *(float4*)&s_stage[(ty * 4 + i) * 68 + d4 * 4];
#pragma unroll
            for (int j = 0; j < 4; j++) wv[j] = *(float4*)&s_W[(tx + 16 * j) * 68 + d4 * 4];
#pragma unroll
            for (int i = 0; i < 4; i++)
#pragma unroll
                for (int j = 0; j < 4; j++) {
                    acc[i][j] += qv[i].x * wv[j].x;
                    acc[i][j] += qv[i].y * wv[j].y;
                    acc[i][j] += qv[i].z * wv[j].z;
                    acc[i][j] += qv[i].w * wv[j].w;
                }
        }
#pragma unroll
        for (int i = 0; i < 4; i++)
#pragma unroll
            for (int j = 0; j < 4; j++)
                s_qp[(ty * 4 + i) * 65 + tx + 16 * j] = acc[i][j];
    }
    __syncthreads();   // protects stage reuse below

    // ---- load x chunk [128][64] and Wk [64][64] ----
#pragma unroll
    for (int i = 0; i < 8; i++) {
        int idx = tid + 256 * i; int k = idx >> 4, d4 = idx & 15;
        *(float4*)&s_stage[k * 68 + d4 * 4] =
            *(const float4*)&x[((size_t)b * KS_ + kc * KC_ + k) * KD_ + h * DH_ + d4 * 4];
    }
#pragma unroll
    for (int i = 0; i < 4; i++) {
        int idx = tid + 256 * i; int a = idx >> 4, d4 = idx & 15;
        *(float4*)&s_W[a * 68 + d4 * 4] =
            *(const float4*)&W[a * 128 + d4 * 4];
    }
    __syncthreads();

    // ---- kpb[k][a] = sum_d kh[k][d]*Wk[a][d]   (k = ty*8+i, a = tx+16j)
    {
        float acc[8][4];
#pragma unroll
        for (int i = 0; i < 8; i++)
#pragma unroll
            for (int j = 0; j < 4; j++) acc[i][j] = 0.f;
#pragma unroll
        for (int d4 = 0; d4 < 16; d4++) {
            float4 kv[8], wv[4];
#pragma unroll
            for (int i = 0; i < 8; i++) kv[i] = *(float4*)&s_stage[(ty * 8 + i) * 68 + d4 * 4];
#pragma unroll
            for (int j = 0; j < 4; j++) wv[j] = *(float4*)&s_W[(tx + 16 * j) * 68 + d4 * 4];
#pragma unroll
            for (int i = 0; i < 8; i++)
#pragma unroll
                for (int j = 0; j < 4; j++) {
                    acc[i][j] += kv[i].x * wv[j].x;
                    acc[i][j] += kv[i].y * wv[j].y;
                    acc[i][j] += kv[i].z * wv[j].z;
                    acc[i][j] += kv[i].w * wv[j].w;
                }
        }
#pragma unroll
        for (int i = 0; i < 8; i++)
#pragma unroll
            for (int j = 0; j < 4; j++)
                s_kpb[(ty * 8 + i) * 65 + tx + 16 * j] = acc[i][j];
    }
    __syncthreads();

    // ---- scores[q][k] = sum_a w2[a]*tanh(qp[q][a] + kpb[k][a])
    //      q = ty*4+j  (ty<16),  k = tx + 16*i (i<8)
    {
        float acc[4][8];
#pragma unroll
        for (int j = 0; j < 4; j++)
#pragma unroll
            for (int i = 0; i < 8; i++) acc[j][i] = 0.f;

#pragma unroll 4
        for (int a = 0; a < A_; a++) {
            float w2a = s_w2[a];
            float qv[4], kv[8];
#pragma unroll
            for (int j = 0; j < 4; j++) qv[j] = s_qp[(ty * 4 + j) * 65 + a];
#pragma unroll
            for (int i = 0; i < 8; i++) kv[i] = s_kpb[(tx + 16 * i) * 65 + a];
#pragma unroll
            for (int j = 0; j < 4; j++)
#pragma unroll
                for (int i = 0; i < 8; i++)
                    acc[j][i] += w2a * fast_tanh(qv[j] + kv[i]);
        }

        size_t base = ((size_t)(b * H_ + h) * QS_) * KS_ + kc * KC_;
#pragma unroll
        for (int j = 0; j < 4; j++)
#pragma unroll
            for (int i = 0; i < 8; i++)
                g_scores[base + (size_t)(ty * 4 + j) * KS_ + tx + 16 * i] = acc[j][i];
    }
}

// ---------------- kernel 2: softmax + attention*V ----------------
// smem (floats): s_p 64*129 = 8256 @0 ; s_v 128*68 = 8704 @8256 ;
//                s_m 64 @16960 ; s_inv 64 @17024  -> total 17088
#define SM2_FLOATS 17088

__global__ void __launch_bounds__(256) av_kernel(
    const float* __restrict__ x, const unsigned char* __restrict__ mask,
    float* __restrict__ out)
{
    extern __shared__ float sm[];
    float* s_p   = sm;
    float* s_v   = sm + 8256;
    float* s_m   = sm + 16960;
    float* s_inv = sm + 17024;

    const int h = blockIdx.x, b = blockIdx.y;
    const int tid = threadIdx.x, lane = tid & 31, warp = tid >> 5;
    const size_t sbase = (size_t)(b * H_ + h) * QS_ * KS_;
    const float NEG_INF = __int_as_float(0xff800000);

    // mask bits for this lane's k positions (same across all q rows)
    bool mk[16];
#pragma unroll
    for (int i = 0; i < 16; i++) mk[i] = (mask[b * KS_ + lane + 32 * i] != 0);

    // ---- pass 1: row max + sum-exp (warp per 8 rows) ----
    for (int r = 0; r < 8; r++) {
        int q = warp * 8 + r;
        float v[16];
        float mx = NEG_INF;
#pragma unroll
        for (int i = 0; i < 16; i++) {
            float s = g_scores[sbase + (size_t)q * KS_ + lane + 32 * i];
            if (mk[i]) s = NEG_INF;
            v[i] = s;
            mx = fmaxf(mx, s);
        }
#pragma unroll
        for (int o = 16; o; o >>= 1) mx = fmaxf(mx, __shfl_xor_sync(0xffffffffu, mx, o));
        float sum = 0.f;
#pragma unroll
        for (int i = 0; i < 16; i++) sum += __expf(v[i] - mx);
#pragma unroll
        for (int o = 16; o; o >>= 1) sum += __shfl_xor_sync(0xffffffffu, sum, o);
        if (lane == 0) { s_m[q] = mx; s_inv[q] = 1.f / sum; }
    }
    __syncthreads();

    // ---- pass 2: chunked p @ V ----
    const int tx = tid & 15, ty = tid >> 4;
    const int d0 = tx * 4, q0 = ty * 4;
    float4 acc4[4];
#pragma unroll
    for (int j = 0; j < 4; j++) acc4[j] = make_float4(0.f, 0.f, 0.f, 0.f);

    for (int kcc = 0; kcc < 4; kcc++) {
        // p chunk [64][128]
#pragma unroll
        for (int i = 0; i < 32; i++) {
            int idx = tid + 256 * i; int q = idx >> 7, k = idx & 127;
            int kg = kcc * 128 + k;
            float s = g_scores[sbase + (size_t)q * KS_ + kg];
            float p = mask[b * KS_ + kg] ? 0.f : __expf(s - s_m[q]) * s_inv[q];
            s_p[q * 129 + k] = p;
        }
        // v chunk [128][64]
#pragma unroll
        for (int i = 0; i < 8; i++) {
            int idx = tid + 256 * i; int k = idx >> 4, d4 = idx & 15;
            *(float4*)&s_v[k * 68 + d4 * 4] =
                *(const float4*)&x[((size_t)b * KS_ + kcc * 128 + k) * KD_ + h * DH_ + d4 * 4];
        }
        __syncthreads();

#pragma unroll 4
        for (int k = 0; k < 128; k++) {
            float4 vv = *(float4*)&s_v[k * 68 + d0];
#pragma unroll
            for (int j = 0; j < 4; j++) {
                float p = s_p[(q0 + j) * 129 + k];
                acc4[j].x += p * vv.x;
                acc4[j].y += p * vv.y;
                acc4[j].z += p * vv.z;
                acc4[j].w += p * vv.w;
            }
        }
        __syncthreads();
    }

#pragma unroll
    for (int j = 0; j < 4; j++)
        *(float4*)&out[((size_t)b * QS_ + q0 + j) * QD_ + h * DH_ + d0] = acc4[j];
}

// ---------------- launch ----------------
extern "C" void kernel_launch(void* const* d_in, const int* in_sizes, int n_in,
                              void* d_out, int out_size) {
    const float* x     = (const float*)d_in[0];
    const float* query = (const float*)d_in[1];
    const float* W     = (const float*)d_in[2];
    const float* bias  = (const float*)d_in[3];
    const float* w2    = (const float*)d_in[4];
    const unsigned char* mask = (const unsigned char*)d_in[5];
    float* out = (float*)d_out;

    cudaFuncSetAttribute(scores_kernel, cudaFuncAttributeMaxDynamicSharedMemorySize, SM1_FLOATS * 4);
    cudaFuncSetAttribute(av_kernel,     cudaFuncAttributeMaxDynamicSharedMemorySize, SM2_FLOATS * 4);

    scores_kernel<<<dim3(KS_ / KC_, H_, B_), 256, SM1_FLOATS * 4>>>(x, query, W, bias, w2);
    av_kernel<<<dim3(H_, B_), 256, SM2_FLOATS * 4>>>(x, mask, out);
}

// round 2
// speedup vs baseline: 1.0881x; 1.0881x over previous
#include <cuda_runtime.h>
#include <cuda_fp16.h>

#define B_  8
#define H_  8
#define QS_ 64
#define KS_ 512
#define A_  64
#define DH_ 64
#define KC_ 128
#define QD_ 512
#define KD_ 512

// 8 MB scratch for scores [B][H][QS][KS]
__device__ float g_scores[B_*H_*QS_*KS_];

__device__ __forceinline__ __half2 htanh2_fast(__half2 v) {
    unsigned in = *(unsigned*)&v, out;
    asm("tanh.approx.f16x2 %0, %1;" : "=r"(out) : "r"(in));
    return *(__half2*)&out;
}

// ---------------- kernel 1: fused projections + tanh scores ----------------
// smem layout (floats):
//   s_qp    : 64*65  = 4160   @ 0
//   s_kpb   : 128*65 = 8320   @ 4160
//   s_stage : 128*68 = 8704   @ 12480   (query tile, then x chunk)
//   s_W     : 64*68  = 4352   @ 21184   (Wq, then Wk)
//   s_bias  : 64              @ 25536
//   s_w2    : 64              @ 25600
#define SM1_FLOATS 25664

__global__ void __launch_bounds__(256, 2) scores_kernel(
    const float* __restrict__ x, const float* __restrict__ query,
    const float* __restrict__ W, const float* __restrict__ bias,
    const float* __restrict__ w2)
{
    extern __shared__ float sm[];
    float* s_qp    = sm;
    float* s_kpb   = sm + 4160;
    float* s_stage = sm + 12480;
    float* s_W     = sm + 21184;
    float* s_bias  = sm + 25536;
    float* s_w2    = sm + 25600;

    const int kc = blockIdx.x, h = blockIdx.y, b = blockIdx.z;
    const int tid = threadIdx.x;
    const int tx = tid & 15, ty = tid >> 4;

    if (tid < 64) { s_bias[tid] = bias[tid]; s_w2[tid] = w2[tid]; }

    // ---- load query tile [64][64] and Wq [64][64] ----
#pragma unroll
    for (int i = 0; i < 4; i++) {
        int idx = tid + 256 * i; int q = idx >> 4, d4 = idx & 15;
        *(float4*)&s_stage[q * 68 + d4 * 4] =
            *(const float4*)&query[(size_t)(b * QS_ + q) * QD_ + h * DH_ + d4 * 4];
    }
#pragma unroll
    for (int i = 0; i < 4; i++) {
        int idx = tid + 256 * i; int a = idx >> 4, d4 = idx & 15;
        *(float4*)&s_W[a * 68 + d4 * 4] =
            *(const float4*)&W[a * 128 + 64 + d4 * 4];
    }
    __syncthreads();

    // ---- qp[q][a] = sum_d qh[q][d]*Wq[a][d] + bias[a]   (a = tx + 16j)
    {
        float acc[4][4];
#pragma unroll
        for (int j = 0; j < 4; j++) {
            float bv = s_bias[tx + 16 * j];
#pragma unroll
            for (int i = 0; i < 4; i++) acc[i][j] = bv;
        }
#pragma unroll
        for (int d4 = 0; d4 < 16; d4++) {
            float4 qv[4], wv[4];
#pragma unroll
            for (int i = 0; i < 4; i++) qv[i] = *(float4*)&s_stage[(ty * 4 + i) * 68 + d4 * 4];
#pragma unroll
            for (int j = 0; j < 4; j++) wv[j] = *(float4*)&s_W[(tx + 16 * j) * 68 + d4 * 4];
#pragma unroll
            for (int i = 0; i < 4; i++)
#pragma unroll
                for (int j = 0; j < 4; j++) {
                    acc[i][j] += qv[i].x * wv[j].x;
                    acc[i][j] += qv[i].y * wv[j].y;
                    acc[i][j] += qv[i].z * wv[j].z;
                    acc[i][j] += qv[i].w * wv[j].w;
                }
        }
#pragma unroll
        for (int i = 0; i < 4; i++)
#pragma unroll
            for (int j = 0; j < 4; j++)
                s_qp[(ty * 4 + i) * 65 + tx + 16 * j] = acc[i][j];
    }
    __syncthreads();   // protects stage reuse below

    // ---- load x chunk [128][64] and Wk [64][64] ----
#pragma unroll
    for (int i = 0; i < 8; i++) {
        int idx = tid + 256 * i; int k = idx >> 4, d4 = idx & 15;
        *(float4*)&s_stage[k * 68 + d4 * 4] =
            *(const float4*)&x[((size_t)b * KS_ + kc * KC_ + k) * KD_ + h * DH_ + d4 * 4];
    }
#pragma unroll
    for (int i = 0; i < 4; i++) {
        int idx = tid + 256 * i; int a = idx >> 4, d4 = idx & 15;
        *(float4*)&s_W[a * 68 + d4 * 4] =
            *(const float4*)&W[a * 128 + d4 * 4];
    }
    __syncthreads();

    // ---- kpb[k][a] = sum_d kh[k][d]*Wk[a][d]   (k = ty*8+i, a = tx+16j)
    {
        float acc[8][4];
#pragma unroll
        for (int i = 0; i < 8; i++)
#pragma unroll
            for (int j = 0; j < 4; j++) acc[i][j] = 0.f;
#pragma unroll
        for (int d4 = 0; d4 < 16; d4++) {
            float4 kv[8], wv[4];
#pragma unroll
            for (int i = 0; i < 8; i++) kv[i] = *(float4*)&s_stage[(ty * 8 + i) * 68 + d4 * 4];
#pragma unroll
            for (int j = 0; j < 4; j++) wv[j] = *(float4*)&s_W[(tx + 16 * j) * 68 + d4 * 4];
#pragma unroll
            for (int i = 0; i < 8; i++)
#pragma unroll
                for (int j = 0; j < 4; j++) {
                    acc[i][j] += kv[i].x * wv[j].x;
                    acc[i][j] += kv[i].y * wv[j].y;
                    acc[i][j] += kv[i].z * wv[j].z;
                    acc[i][j] += kv[i].w * wv[j].w;
                }
        }
#pragma unroll
        for (int i = 0; i < 8; i++)
#pragma unroll
            for (int j = 0; j < 4; j++)
                s_kpb[(ty * 8 + i) * 65 + tx + 16 * j] = acc[i][j];
    }
    __syncthreads();

    // ---- scores[q][k] = sum_a w2[a]*tanh(qp[q][a] + kpb[k][a])
    //      q = ty*4+j (ty<16), k = tx + 16*i (i<8), f16x2-paired over i
    {
        float acc[4][8];
#pragma unroll
        for (int j = 0; j < 4; j++)
#pragma unroll
            for (int i = 0; i < 8; i++) acc[j][i] = 0.f;

#pragma unroll 2
        for (int a = 0; a < A_; a++) {
            float w2a = s_w2[a];
            // pack the 8 k-projection values into 4 half2
            __half2 kh[4];
#pragma unroll
            for (int i = 0; i < 4; i++)
                kh[i] = __floats2half2_rn(s_kpb[(tx + 16 * (2 * i)) * 65 + a],
                                          s_kpb[(tx + 16 * (2 * i + 1)) * 65 + a]);
#pragma unroll
            for (int j = 0; j < 4; j++) {
                __half2 qh2 = __half2half2(__float2half_rn(s_qp[(ty * 4 + j) * 65 + a]));
#pragma unroll
                for (int i = 0; i < 4; i++) {
                    __half2 t = htanh2_fast(__hadd2(qh2, kh[i]));
                    float2 f = __half22float2(t);
                    acc[j][2 * i]     += w2a * f.x;
                    acc[j][2 * i + 1] += w2a * f.y;
                }
            }
        }

        size_t base = ((size_t)(b * H_ + h) * QS_) * KS_ + kc * KC_;
#pragma unroll
        for (int j = 0; j < 4; j++)
#pragma unroll
            for (int i = 0; i < 8; i++)
                g_scores[base + (size_t)(ty * 4 + j) * KS_ + tx + 16 * i] = acc[j][i];
    }
}

// ---------------- kernel 2: softmax + attention*V (q-quarter split) ----------------
// Each CTA: 16 q rows of one (b,h).
// smem (floats): s_p 16*129 = 2064 @0 ; s_v 128*68 = 8704 @2064 ;
//                s_m 16 @10768 ; s_inv 16 @10784  -> total 10800
#define SM2_FLOATS 10800

__global__ void __launch_bounds__(256, 2) av_kernel(
    const float* __restrict__ x, const unsigned char* __restrict__ mask,
    float* __restrict__ out)
{
    extern __shared__ float sm[];
    float* s_p   = sm;
    float* s_v   = sm + 2064;
    float* s_m   = sm + 10768;
    float* s_inv = sm + 10784;

    const int qq = blockIdx.x, h = blockIdx.y, b = blockIdx.z;
    const int tid = threadIdx.x, lane = tid & 31, warp = tid >> 5;
    const size_t sbase = (size_t)(b * H_ + h) * QS_ * KS_ + (size_t)qq * 16 * KS_;
    const float NEG_INF = __int_as_float(0xff800000);

    // mask bits for this lane's k positions (shared across rows)
    bool mk[16];
#pragma unroll
    for (int i = 0; i < 16; i++) mk[i] = (mask[b * KS_ + lane + 32 * i] != 0);

    // ---- pass 1: row max + sum-exp (each warp: 2 of the 16 rows) ----
#pragma unroll
    for (int r = 0; r < 2; r++) {
        int ql = warp * 2 + r;
        float v[16];
        float mx = NEG_INF;
#pragma unroll
        for (int i = 0; i < 16; i++) {
            float s = g_scores[sbase + (size_t)ql * KS_ + lane + 32 * i];
            if (mk[i]) s = NEG_INF;
            v[i] = s;
            mx = fmaxf(mx, s);
        }
#pragma unroll
        for (int o = 16; o; o >>= 1) mx = fmaxf(mx, __shfl_xor_sync(0xffffffffu, mx, o));
        float sum = 0.f;
#pragma unroll
        for (int i = 0; i < 16; i++) sum += __expf(v[i] - mx);
#pragma unroll
        for (int o = 16; o; o >>= 1) sum += __shfl_xor_sync(0xffffffffu, sum, o);
        if (lane == 0) { s_m[ql] = mx; s_inv[ql] = 1.f / sum; }
    }
    __syncthreads();

    // ---- pass 2: chunked p @ V ----
    const int tx = tid & 15, ty = tid >> 4;   // ty = local q row, tx*4 = d0
    const int d0 = tx * 4;
    float4 acc4 = make_float4(0.f, 0.f, 0.f, 0.f);

    for (int kcc = 0; kcc < 4; kcc++) {
        // p chunk [16][128]
#pragma unroll
        for (int i = 0; i < 8; i++) {
            int idx = tid + 256 * i; int q = idx >> 7, k = idx & 127;
            int kg = kcc * 128 + k;
            float s = g_scores[sbase + (size_t)q * KS_ + kg];
            float p = mask[b * KS_ + kg] ? 0.f : __expf(s - s_m[q]) * s_inv[q];
            s_p[q * 129 + k] = p;
        }
        // v chunk [128][64]
#pragma unroll
        for (int i = 0; i < 8; i++) {
            int idx = tid + 256 * i; int k = idx >> 4, d4 = idx & 15;
            *(float4*)&s_v[k * 68 + d4 * 4] =
                *(const float4*)&x[((size_t)b * KS_ + kcc * 128 + k) * KD_ + h * DH_ + d4 * 4];
        }
        __syncthreads();

#pragma unroll 8
        for (int k = 0; k < 128; k++) {
            float4 vv = *(float4*)&s_v[k * 68 + d0];
            float p = s_p[ty * 129 + k];
            acc4.x += p * vv.x;
            acc4.y += p * vv.y;
            acc4.z += p * vv.z;
            acc4.w += p * vv.w;
        }
        __syncthreads();
    }

    *(float4*)&out[((size_t)(b * QS_ + qq * 16 + ty)) * QD_ + h * DH_ + d0] = acc4;
}

// ---------------- launch ----------------
extern "C" void kernel_launch(void* const* d_in, const int* in_sizes, int n_in,
                              void* d_out, int out_size) {
    const float* x     = (const float*)d_in[0];
    const float* query = (const float*)d_in[1];
    const float* W     = (const float*)d_in[2];
    const float* bias  = (const float*)d_in[3];
    const float* w2    = (const float*)d_in[4];
    const unsigned char* mask = (const unsigned char*)d_in[5];
    float* out = (float*)d_out;

    cudaFuncSetAttribute(scores_kernel, cudaFuncAttributeMaxDynamicSharedMemorySize, SM1_FLOATS * 4);
    cudaFuncSetAttribute(av_kernel,     cudaFuncAttributeMaxDynamicSharedMemorySize, SM2_FLOATS * 4);

    scores_kernel<<<dim3(KS_ / KC_, H_, B_), 256, SM1_FLOATS * 4>>>(x, query, W, bias, w2);
    av_kernel<<<dim3(4, H_, B_), 256, SM2_FLOATS * 4>>>(x, mask, out);
}

// round 3
// speedup vs baseline: 1.2290x; 1.1295x over previous
#include <cuda_runtime.h>
#include <cuda_fp16.h>

#define B_  8
#define H_  8
#define QS_ 64
#define KS_ 512
#define A_  64
#define DH_ 64
#define KC_ 128
#define QD_ 512
#define KD_ 512

typedef unsigned long long ull;

__device__ float g_scores[B_*H_*QS_*KS_];

__device__ __forceinline__ __half2 htanh2_fast(__half2 v) {
    unsigned in = *(unsigned*)&v, out;
    asm("tanh.approx.f16x2 %0, %1;" : "=r"(out) : "r"(in));
    return *(__half2*)&out;
}
__device__ __forceinline__ ull pk2(float x, float y) {
    ull r; asm("mov.b64 %0, {%1, %2};" : "=l"(r) : "f"(x), "f"(y)); return r;
}
__device__ __forceinline__ float2 upk2(ull v) {
    float2 r; asm("mov.b64 {%0, %1}, %2;" : "=f"(r.x), "=f"(r.y) : "l"(v)); return r;
}
__device__ __forceinline__ ull ffma2(ull a, ull b, ull c) {
    ull d; asm("fma.rn.f32x2 %0, %1, %2, %3;" : "=l"(d) : "l"(a), "l"(b), "l"(c)); return d;
}
__device__ __forceinline__ ull fadd2(ull a, ull b) {
    ull d; asm("add.rn.f32x2 %0, %1, %2;" : "=l"(d) : "l"(a), "l"(b)); return d;
}

// ================= kernel 1: projections (f32x2 GEMM) + f16x2 tanh scores ==========
// smem (bytes):
//   s_stage f32[128][68]  @0      34816
//   s_W     f32[64][68]   @34816  17408
//   s_qph   half[64][72]  @52224   9216
//   s_kph   half[64][136] @61440  17408
//   s_bias  f32[64]       @78848    256
//   s_w2h   half2[32]     @79104    128
#define SM1_BYTES 79360

__global__ void __launch_bounds__(256, 2) scores_kernel(
    const float* __restrict__ x, const float* __restrict__ query,
    const float* __restrict__ W, const float* __restrict__ bias,
    const float* __restrict__ w2)
{
    extern __shared__ char sm1[];
    float*   s_stage = (float*)sm1;
    float*   s_W     = (float*)(sm1 + 34816);
    __half*  s_qph   = (__half*)(sm1 + 52224);
    __half*  s_kph   = (__half*)(sm1 + 61440);
    float*   s_bias  = (float*)(sm1 + 78848);
    __half2* s_w2h   = (__half2*)(sm1 + 79104);

    const int kc = blockIdx.x, h = blockIdx.y, b = blockIdx.z;
    const int tid = threadIdx.x;
    const int tx = tid & 15, ty = tid >> 4;

    if (tid < 64) s_bias[tid] = bias[tid];
    if (tid < 32) s_w2h[tid] = __floats2half2_rn(w2[2*tid], w2[2*tid+1]);

    // ---- stage query [64][64] + Wq ----
#pragma unroll
    for (int i = 0; i < 4; i++) {
        int idx = tid + 256 * i; int q = idx >> 4, d4 = idx & 15;
        *(float4*)&s_stage[q * 68 + d4 * 4] =
            *(const float4*)&query[(size_t)(b * QS_ + q) * QD_ + h * DH_ + d4 * 4];
    }
#pragma unroll
    for (int i = 0; i < 4; i++) {
        int idx = tid + 256 * i; int a = idx >> 4, d4 = idx & 15;
        *(float4*)&s_W[a * 68 + d4 * 4] = *(const float4*)&W[a * 128 + 64 + d4 * 4];
    }
    __syncthreads();

    // ---- qp GEMM (f32x2, pairs over d parity), write half to s_qph[a][q] ----
    {
        ull acc2[4][4];
#pragma unroll
        for (int i = 0; i < 4; i++)
#pragma unroll
            for (int j = 0; j < 4; j++) acc2[i][j] = 0ULL;
#pragma unroll
        for (int d4 = 0; d4 < 16; d4++) {
            ull qv[4][2], wv[4][2];
#pragma unroll
            for (int i = 0; i < 4; i++) {
                float4 v = *(float4*)&s_stage[(ty * 4 + i) * 68 + d4 * 4];
                qv[i][0] = pk2(v.x, v.y); qv[i][1] = pk2(v.z, v.w);
            }
#pragma unroll
            for (int j = 0; j < 4; j++) {
                float4 v = *(float4*)&s_W[(tx + 16 * j) * 68 + d4 * 4];
                wv[j][0] = pk2(v.x, v.y); wv[j][1] = pk2(v.z, v.w);
            }
#pragma unroll
            for (int i = 0; i < 4; i++)
#pragma unroll
                for (int j = 0; j < 4; j++) {
                    acc2[i][j] = ffma2(qv[i][0], wv[j][0], acc2[i][j]);
                    acc2[i][j] = ffma2(qv[i][1], wv[j][1], acc2[i][j]);
                }
        }
#pragma unroll
        for (int i = 0; i < 4; i++)
#pragma unroll
            for (int j = 0; j < 4; j++) {
                float2 p = upk2(acc2[i][j]);
                float v = p.x + p.y + s_bias[tx + 16 * j];
                s_qph[(tx + 16 * j) * 72 + ty * 4 + i] = __float2half_rn(v);
            }
    }
    __syncthreads();

    // ---- stage x chunk [128][64] + Wk ----
#pragma unroll
    for (int i = 0; i < 8; i++) {
        int idx = tid + 256 * i; int k = idx >> 4, d4 = idx & 15;
        *(float4*)&s_stage[k * 68 + d4 * 4] =
            *(const float4*)&x[((size_t)b * KS_ + kc * KC_ + k) * KD_ + h * DH_ + d4 * 4];
    }
#pragma unroll
    for (int i = 0; i < 4; i++) {
        int idx = tid + 256 * i; int a = idx >> 4, d4 = idx & 15;
        *(float4*)&s_W[a * 68 + d4 * 4] = *(const float4*)&W[a * 128 + d4 * 4];
    }
    __syncthreads();

    // ---- kpb GEMM (f32x2), write half to s_kph[a][k] ----
    {
        ull acc2[8][4];
#pragma unroll
        for (int i = 0; i < 8; i++)
#pragma unroll
            for (int j = 0; j < 4; j++) acc2[i][j] = 0ULL;
#pragma unroll
        for (int d4 = 0; d4 < 16; d4++) {
            ull kv[8][2], wv[4][2];
#pragma unroll
            for (int i = 0; i < 8; i++) {
                float4 v = *(float4*)&s_stage[(ty * 8 + i) * 68 + d4 * 4];
                kv[i][0] = pk2(v.x, v.y); kv[i][1] = pk2(v.z, v.w);
            }
#pragma unroll
            for (int j = 0; j < 4; j++) {
                float4 v = *(float4*)&s_W[(tx + 16 * j) * 68 + d4 * 4];
                wv[j][0] = pk2(v.x, v.y); wv[j][1] = pk2(v.z, v.w);
            }
#pragma unroll
            for (int i = 0; i < 8; i++)
#pragma unroll
                for (int j = 0; j < 4; j++) {
                    acc2[i][j] = ffma2(kv[i][0], wv[j][0], acc2[i][j]);
                    acc2[i][j] = ffma2(kv[i][1], wv[j][1], acc2[i][j]);
                }
        }
#pragma unroll
        for (int i = 0; i < 8; i++)
#pragma unroll
            for (int j = 0; j < 4; j++) {
                float2 p = upk2(acc2[i][j]);
                s_kph[(tx + 16 * j) * 136 + ty * 8 + i] = __float2half_rn(p.x + p.y);
            }
    }
    __syncthreads();

    // ---- scores[q][k] = sum_a w2[a] * tanh(qp[q][a] + kpb[k][a])
    //      thread: q0 = ty*4 (4 rows), k0 = tx*8 (8 cols, f16x2 over k-pairs)
    {
        ull acc2[4][4];   // [q][k-pair] f32x2 over adjacent k
#pragma unroll
        for (int j = 0; j < 4; j++)
#pragma unroll
            for (int i = 0; i < 4; i++) acc2[j][i] = 0ULL;

        const int q0 = ty * 4, k0 = tx * 8;
#pragma unroll 2
        for (int a2 = 0; a2 < 32; a2++) {
            int a = 2 * a2;
            uint4 kAu = *(uint4*)&s_kph[a * 136 + k0];
            uint4 kBu = *(uint4*)&s_kph[(a + 1) * 136 + k0];
            uint2 qAu = *(uint2*)&s_qph[a * 72 + q0];
            uint2 qBu = *(uint2*)&s_qph[(a + 1) * 72 + q0];
            __half2 w2p = s_w2h[a2];
            __half2 w2lo = __half2half2(__low2half(w2p));
            __half2 w2hi = __half2half2(__high2half(w2p));
            const __half2* kA = (const __half2*)&kAu;
            const __half2* kB = (const __half2*)&kBu;
            const __half*  qA = (const __half*)&qAu;
            const __half*  qB = (const __half*)&qBu;
#pragma unroll
            for (int j = 0; j < 4; j++) {
                __half2 qa2 = __half2half2(qA[j]);
                __half2 qb2 = __half2half2(qB[j]);
#pragma unroll
                for (int i = 0; i < 4; i++) {
                    __half2 tA = htanh2_fast(__hadd2(qa2, kA[i]));
                    __half2 tB = htanh2_fast(__hadd2(qb2, kB[i]));
                    __half2 part = __hfma2(w2hi, tB, __hmul2(w2lo, tA));
                    float2 pf = __half22float2(part);
                    acc2[j][i] = fadd2(acc2[j][i], pk2(pf.x, pf.y));
                }
            }
        }

        size_t base = ((size_t)(b * H_ + h) * QS_) * KS_ + kc * KC_;
#pragma unroll
        for (int j = 0; j < 4; j++)
#pragma unroll
            for (int i = 0; i < 4; i++) {
                float2 p = upk2(acc2[j][i]);
                *(float2*)&g_scores[base + (size_t)(q0 + j) * KS_ + k0 + 2 * i] = p;
            }
    }
}

// ================= kernel 2: softmax + p@V (8q x 8d tile, f32x2, k-split) ==========
// CTA: 32 q rows x 64 d of one (b,h).  256 thr: tx(8)=d-group, tyq(4)=q-group, kg(8)=k-group.
// smem (bytes):
//   s_p   f32[128][36] @0      18432   (transposed: [k][q])
//   s_v   f32[128][68] @18432  34816
//   s_red f32[4][32][68] @53248 34816
//   s_m   f32[32] @88064 ; s_inv f32[32] @88192
#define SM2_BYTES 88320

__global__ void __launch_bounds__(256, 1) av_kernel(
    const float* __restrict__ x, const unsigned char* __restrict__ mask,
    float* __restrict__ out)
{
    extern __shared__ char sm2[];
    float* s_p   = (float*)sm2;
    float* s_v   = (float*)(sm2 + 18432);
    float* s_red = (float*)(sm2 + 53248);
    float* s_m   = (float*)(sm2 + 88064);
    float* s_inv = (float*)(sm2 + 88192);

    const int qq = blockIdx.x, h = blockIdx.y, b = blockIdx.z;
    const int tid = threadIdx.x, lane = tid & 31, warp = tid >> 5;
    const size_t sbase = (size_t)(b * H_ + h) * QS_ * KS_ + (size_t)qq * 32 * KS_;
    const float NEG_INF = __int_as_float(0xff800000);

    // ---- pass 1: row max + sum-exp (warp handles 4 of the 32 rows) ----
    {
        bool mk[16];
#pragma unroll
        for (int i = 0; i < 16; i++) mk[i] = (mask[b * KS_ + lane + 32 * i] != 0);
#pragma unroll
        for (int r = 0; r < 4; r++) {
            int ql = warp * 4 + r;
            float v[16], mx = NEG_INF;
#pragma unroll
            for (int i = 0; i < 16; i++) {
                float s = g_scores[sbase + (size_t)ql * KS_ + lane + 32 * i];
                if (mk[i]) s = NEG_INF;
                v[i] = s; mx = fmaxf(mx, s);
            }
#pragma unroll
            for (int o = 16; o; o >>= 1) mx = fmaxf(mx, __shfl_xor_sync(0xffffffffu, mx, o));
            float sum = 0.f;
#pragma unroll
            for (int i = 0; i < 16; i++) sum += __expf(v[i] - mx);
#pragma unroll
            for (int o = 16; o; o >>= 1) sum += __shfl_xor_sync(0xffffffffu, sum, o);
            if (lane == 0) { s_m[ql] = mx; s_inv[ql] = 1.f / sum; }
        }
    }
    __syncthreads();

    // ---- pass 2: chunked p @ V with 8q x 8d register tiles ----
    const int tx = tid & 7;            // d-group: d = 4*tx.. and 32+4*tx..
    const int tyq = (tid >> 3) & 3;    // q-group: q0 = tyq*8
    const int kg = tid >> 5;           // k-group (== warp)
    const int q0 = tyq * 8;

    ull acc2[8][4];                    // [qi][{d:4tx..+1},{+2..3},{32+4tx..+1},{+2..3}]
#pragma unroll
    for (int qi = 0; qi < 8; qi++)
#pragma unroll
        for (int c = 0; c < 4; c++) acc2[qi][c] = 0ULL;

    const int pq = tid & 31;           // q row this thread fills p for
    const int pkb = (tid >> 5) * 16;   // 16-k block this thread fills
    const float pm = s_m[pq], pinv = s_inv[pq];

    for (int cc = 0; cc < 4; cc++) {
        // p chunk: thread reads 16 consecutive k of row pq, stores transposed [k][q]
        {
            const float* gp = &g_scores[sbase + (size_t)pq * KS_ + cc * 128 + pkb];
            const unsigned char* mp = &mask[b * KS_ + cc * 128 + pkb];
#pragma unroll
            for (int j4 = 0; j4 < 4; j4++) {
                float4 s4 = *(const float4*)&gp[j4 * 4];
                float p0 = mp[j4*4+0] ? 0.f : __expf(s4.x - pm) * pinv;
                float p1 = mp[j4*4+1] ? 0.f : __expf(s4.y - pm) * pinv;
                float p2 = mp[j4*4+2] ? 0.f : __expf(s4.z - pm) * pinv;
                float p3 = mp[j4*4+3] ? 0.f : __expf(s4.w - pm) * pinv;
                s_p[(pkb + j4*4 + 0) * 36 + pq] = p0;
                s_p[(pkb + j4*4 + 1) * 36 + pq] = p1;
                s_p[(pkb + j4*4 + 2) * 36 + pq] = p2;
                s_p[(pkb + j4*4 + 3) * 36 + pq] = p3;
            }
        }
        // v chunk [128][64]
#pragma unroll
        for (int i = 0; i < 8; i++) {
            int idx = tid + 256 * i; int k = idx >> 4, d4 = idx & 15;
            *(float4*)&s_v[k * 68 + d4 * 4] =
                *(const float4*)&x[((size_t)b * KS_ + cc * 128 + k) * KD_ + h * DH_ + d4 * 4];
        }
        __syncthreads();

        // main loop: this thread's 16 k of the chunk
#pragma unroll 4
        for (int ki = 0; ki < 16; ki++) {
            int k = kg * 16 + ki;
            float4 va = *(float4*)&s_v[k * 68 + 4 * tx];
            float4 vb = *(float4*)&s_v[k * 68 + 32 + 4 * tx];
            ull v0 = pk2(va.x, va.y), v1 = pk2(va.z, va.w);
            ull v2 = pk2(vb.x, vb.y), v3 = pk2(vb.z, vb.w);
            float4 pa = *(float4*)&s_p[k * 36 + q0];
            float4 pb = *(float4*)&s_p[k * 36 + q0 + 4];
            float pr[8] = {pa.x, pa.y, pa.z, pa.w, pb.x, pb.y, pb.z, pb.w};
#pragma unroll
            for (int qi = 0; qi < 8; qi++) {
                ull p2r = pk2(pr[qi], pr[qi]);
                acc2[qi][0] = ffma2(p2r, v0, acc2[qi][0]);
                acc2[qi][1] = ffma2(p2r, v1, acc2[qi][1]);
                acc2[qi][2] = ffma2(p2r, v2, acc2[qi][2]);
                acc2[qi][3] = ffma2(p2r, v3, acc2[qi][3]);
            }
        }
        __syncthreads();
    }

    // ---- tree reduction over the 8 k-groups ----
    // round A: kg 4-7 store, kg 0-3 add
    if (kg >= 4) {
#pragma unroll
        for (int qi = 0; qi < 8; qi++) {
            int row = (kg - 4) * 32 + q0 + qi;
            float2 a0 = upk2(acc2[qi][0]), a1 = upk2(acc2[qi][1]);
            float2 a2v = upk2(acc2[qi][2]), a3 = upk2(acc2[qi][3]);
            *(float4*)&s_red[row * 68 + 4 * tx]      = make_float4(a0.x, a0.y, a1.x, a1.y);
            *(float4*)&s_red[row * 68 + 32 + 4 * tx] = make_float4(a2v.x, a2v.y, a3.x, a3.y);
        }
    }
    __syncthreads();
    if (kg < 4) {
#pragma unroll
        for (int qi = 0; qi < 8; qi++) {
            int row = kg * 32 + q0 + qi;
            float4 r0 = *(float4*)&s_red[row * 68 + 4 * tx];
            float4 r1 = *(float4*)&s_red[row * 68 + 32 + 4 * tx];
            acc2[qi][0] = fadd2(acc2[qi][0], pk2(r0.x, r0.y));
            acc2[qi][1] = fadd2(acc2[qi][1], pk2(r0.z, r0.w));
            acc2[qi][2] = fadd2(acc2[qi][2], pk2(r1.x, r1.y));
            acc2[qi][3] = fadd2(acc2[qi][3], pk2(r1.z, r1.w));
        }
    }
    __syncthreads();
    // round B: kg 2-3 store, kg 0-1 add
    if (kg == 2 || kg == 3) {
#pragma unroll
        for (int qi = 0; qi < 8; qi++) {
            int row = (kg - 2) * 32 + q0 + qi;
            float2 a0 = upk2(acc2[qi][0]), a1 = upk2(acc2[qi][1]);
            float2 a2v = upk2(acc2[qi][2]), a3 = upk2(acc2[qi][3]);
            *(float4*)&s_red[row * 68 + 4 * tx]      = make_float4(a0.x, a0.y, a1.x, a1.y);
            *(float4*)&s_red[row * 68 + 32 + 4 * tx] = make_float4(a2v.x, a2v.y, a3.x, a3.y);
        }
    }
    __syncthreads();
    if (kg < 2) {
#pragma unroll
        for (int qi = 0; qi < 8; qi++) {
            int row = kg * 32 + q0 + qi;
            float4 r0 = *(float4*)&s_red[row * 68 + 4 * tx];
            float4 r1 = *(float4*)&s_red[row * 68 + 32 + 4 * tx];
            acc2[qi][0] = fadd2(acc2[qi][0], pk2(r0.x, r0.y));
            acc2[qi][1] = fadd2(acc2[qi][1], pk2(r0.z, r0.w));
            acc2[qi][2] = fadd2(acc2[qi][2], pk2(r1.x, r1.y));
            acc2[qi][3] = fadd2(acc2[qi][3], pk2(r1.z, r1.w));
        }
    }
    __syncthreads();
    // round C: kg 1 stores, kg 0 adds + writes out
    if (kg == 1) {
#pragma unroll
        for (int qi = 0; qi < 8; qi++) {
            int row = q0 + qi;
            float2 a0 = upk2(acc2[qi][0]), a1 = upk2(acc2[qi][1]);
            float2 a2v = upk2(acc2[qi][2]), a3 = upk2(acc2[qi][3]);
            *(float4*)&s_red[row * 68 + 4 * tx]      = make_float4(a0.x, a0.y, a1.x, a1.y);
            *(float4*)&s_red[row * 68 + 32 + 4 * tx] = make_float4(a2v.x, a2v.y, a3.x, a3.y);
        }
    }
    __syncthreads();
    if (kg == 0) {
#pragma unroll
        for (int qi = 0; qi < 8; qi++) {
            int row = q0 + qi;
            float4 r0 = *(float4*)&s_red[row * 68 + 4 * tx];
            float4 r1 = *(float4*)&s_red[row * 68 + 32 + 4 * tx];
            float2 a0 = upk2(fadd2(acc2[qi][0], pk2(r0.x, r0.y)));
            float2 a1 = upk2(fadd2(acc2[qi][1], pk2(r0.z, r0.w)));
            float2 a2v = upk2(fadd2(acc2[qi][2], pk2(r1.x, r1.y)));
            float2 a3 = upk2(fadd2(acc2[qi][3], pk2(r1.z, r1.w)));
            size_t ob = ((size_t)(b * QS_ + qq * 32 + q0 + qi)) * QD_ + h * DH_;
            *(float4*)&out[ob + 4 * tx]      = make_float4(a0.x, a0.y, a1.x, a1.y);
            *(float4*)&out[ob + 32 + 4 * tx] = make_float4(a2v.x, a2v.y, a3.x, a3.y);
        }
    }
}

// ---------------- launch ----------------
extern "C" void kernel_launch(void* const* d_in, const int* in_sizes, int n_in,
                              void* d_out, int out_size) {
    const float* x     = (const float*)d_in[0];
    const float* query = (const float*)d_in[1];
    const float* W     = (const float*)d_in[2];
    const float* bias  = (const float*)d_in[3];
    const float* w2    = (const float*)d_in[4];
    const unsigned char* mask = (const unsigned char*)d_in[5];
    float* out = (float*)d_out;

    cudaFuncSetAttribute(scores_kernel, cudaFuncAttributeMaxDynamicSharedMemorySize, SM1_BYTES);
    cudaFuncSetAttribute(av_kernel,     cudaFuncAttributeMaxDynamicSharedMemorySize, SM2_BYTES);

    scores_kernel<<<dim3(KS_ / KC_, H_, B_), 256, SM1_BYTES>>>(x, query, W, bias, w2);
    av_kernel<<<dim3(2, H_, B_), 256, SM2_BYTES>>>(x, mask, out);
}

// round 4
// speedup vs baseline: 1.2559x; 1.0219x over previous
#include <cuda_runtime.h>
#include <cuda_fp16.h>

#define B_  8
#define H_  8
#define QS_ 64
#define KS_ 512
#define A_  64
#define DH_ 64
#define KC_ 128
#define QD_ 512
#define KD_ 512

typedef unsigned long long ull;

__device__ float g_scores[B_*H_*QS_*KS_];

__device__ __forceinline__ __half2 htanh2_fast(__half2 v) {
    unsigned in = *(unsigned*)&v, out;
    asm("tanh.approx.f16x2 %0, %1;" : "=r"(out) : "r"(in));
    return *(__half2*)&out;
}
__device__ __forceinline__ ull pk2(float x, float y) {
    ull r; asm("mov.b64 %0, {%1, %2};" : "=l"(r) : "f"(x), "f"(y)); return r;
}
__device__ __forceinline__ float2 upk2(ull v) {
    float2 r; asm("mov.b64 {%0, %1}, %2;" : "=f"(r.x), "=f"(r.y) : "l"(v)); return r;
}
__device__ __forceinline__ ull ffma2(ull a, ull b, ull c) {
    ull d; asm("fma.rn.f32x2 %0, %1, %2, %3;" : "=l"(d) : "l"(a), "l"(b), "l"(c)); return d;
}
__device__ __forceinline__ ull fadd2(ull a, ull b) {
    ull d; asm("add.rn.f32x2 %0, %1, %2;" : "=l"(d) : "l"(a), "l"(b)); return d;
}

// ================= kernel 1: projections (f32x2 GEMM) + lean f16x2 tanh scores ======
// smem (bytes):
//   s_stage f32[128][68]  @0      34816
//   s_W     f32[64][68]   @34816  17408
//   s_qph   half[64][72]  @52224   9216
//   s_kph   half[64][136] @61440  17408
//   s_bias  f32[64]       @78848    256
//   s_w2s   half2[64]     @79104    256   (splatted w2)
#define SM1_BYTES 79360

__global__ void __launch_bounds__(256, 2) scores_kernel(
    const float* __restrict__ x, const float* __restrict__ query,
    const float* __restrict__ W, const float* __restrict__ bias,
    const float* __restrict__ w2)
{
    extern __shared__ char sm1[];
    float*   s_stage = (float*)sm1;
    float*   s_W     = (float*)(sm1 + 34816);
    __half*  s_qph   = (__half*)(sm1 + 52224);
    __half*  s_kph   = (__half*)(sm1 + 61440);
    float*   s_bias  = (float*)(sm1 + 78848);
    __half2* s_w2s   = (__half2*)(sm1 + 79104);

    const int kc = blockIdx.x, h = blockIdx.y, b = blockIdx.z;
    const int tid = threadIdx.x;
    const int tx = tid & 15, ty = tid >> 4;

    if (tid < 64) {
        s_bias[tid] = bias[tid];
        s_w2s[tid] = __half2half2(__float2half_rn(w2[tid]));
    }

    // ---- stage query [64][64] + Wq ----
#pragma unroll
    for (int i = 0; i < 4; i++) {
        int idx = tid + 256 * i; int q = idx >> 4, d4 = idx & 15;
        *(float4*)&s_stage[q * 68 + d4 * 4] =
            *(const float4*)&query[(size_t)(b * QS_ + q) * QD_ + h * DH_ + d4 * 4];
    }
#pragma unroll
    for (int i = 0; i < 4; i++) {
        int idx = tid + 256 * i; int a = idx >> 4, d4 = idx & 15;
        *(float4*)&s_W[a * 68 + d4 * 4] = *(const float4*)&W[a * 128 + 64 + d4 * 4];
    }
    __syncthreads();

    // ---- qp GEMM (f32x2), write half to s_qph[a][q] ----
    {
        ull acc2[4][4];
#pragma unroll
        for (int i = 0; i < 4; i++)
#pragma unroll
            for (int j = 0; j < 4; j++) acc2[i][j] = 0ULL;
#pragma unroll
        for (int d4 = 0; d4 < 16; d4++) {
            ull qv[4][2], wv[4][2];
#pragma unroll
            for (int i = 0; i < 4; i++) {
                float4 v = *(float4*)&s_stage[(ty * 4 + i) * 68 + d4 * 4];
                qv[i][0] = pk2(v.x, v.y); qv[i][1] = pk2(v.z, v.w);
            }
#pragma unroll
            for (int j = 0; j < 4; j++) {
                float4 v = *(float4*)&s_W[(tx + 16 * j) * 68 + d4 * 4];
                wv[j][0] = pk2(v.x, v.y); wv[j][1] = pk2(v.z, v.w);
            }
#pragma unroll
            for (int i = 0; i < 4; i++)
#pragma unroll
                for (int j = 0; j < 4; j++) {
                    acc2[i][j] = ffma2(qv[i][0], wv[j][0], acc2[i][j]);
                    acc2[i][j] = ffma2(qv[i][1], wv[j][1], acc2[i][j]);
                }
        }
#pragma unroll
        for (int i = 0; i < 4; i++)
#pragma unroll
            for (int j = 0; j < 4; j++) {
                float2 p = upk2(acc2[i][j]);
                float v = p.x + p.y + s_bias[tx + 16 * j];
                s_qph[(tx + 16 * j) * 72 + ty * 4 + i] = __float2half_rn(v);
            }
    }
    __syncthreads();

    // ---- stage x chunk [128][64] + Wk ----
#pragma unroll
    for (int i = 0; i < 8; i++) {
        int idx = tid + 256 * i; int k = idx >> 4, d4 = idx & 15;
        *(float4*)&s_stage[k * 68 + d4 * 4] =
            *(const float4*)&x[((size_t)b * KS_ + kc * KC_ + k) * KD_ + h * DH_ + d4 * 4];
    }
#pragma unroll
    for (int i = 0; i < 4; i++) {
        int idx = tid + 256 * i; int a = idx >> 4, d4 = idx & 15;
        *(float4*)&s_W[a * 68 + d4 * 4] = *(const float4*)&W[a * 128 + d4 * 4];
    }
    __syncthreads();

    // ---- kpb GEMM (f32x2), write half to s_kph[a][k] ----
    {
        ull acc2[8][4];
#pragma unroll
        for (int i = 0; i < 8; i++)
#pragma unroll
            for (int j = 0; j < 4; j++) acc2[i][j] = 0ULL;
#pragma unroll
        for (int d4 = 0; d4 < 16; d4++) {
            ull kv[8][2], wv[4][2];
#pragma unroll
            for (int i = 0; i < 8; i++) {
                float4 v = *(float4*)&s_stage[(ty * 8 + i) * 68 + d4 * 4];
                kv[i][0] = pk2(v.x, v.y); kv[i][1] = pk2(v.z, v.w);
            }
#pragma unroll
            for (int j = 0; j < 4; j++) {
                float4 v = *(float4*)&s_W[(tx + 16 * j) * 68 + d4 * 4];
                wv[j][0] = pk2(v.x, v.y); wv[j][1] = pk2(v.z, v.w);
            }
#pragma unroll
            for (int i = 0; i < 8; i++)
#pragma unroll
                for (int j = 0; j < 4; j++) {
                    acc2[i][j] = ffma2(kv[i][0], wv[j][0], acc2[i][j]);
                    acc2[i][j] = ffma2(kv[i][1], wv[j][1], acc2[i][j]);
                }
        }
#pragma unroll
        for (int i = 0; i < 8; i++)
#pragma unroll
            for (int j = 0; j < 4; j++) {
                float2 p = upk2(acc2[i][j]);
                s_kph[(tx + 16 * j) * 136 + ty * 8 + i] = __float2half_rn(p.x + p.y);
            }
    }
    __syncthreads();

    // ---- scores[q][k] = sum_a w2[a] * tanh(qp[q][a] + kpb[k][a])
    //      lean core: HADD2 + tanh.f16x2 + HFMA2 only; half2 acc over 4 a's.
    {
        const int q0 = ty * 4, k0 = tx * 8;
        float accf[4][8];
#pragma unroll
        for (int j = 0; j < 4; j++)
#pragma unroll
            for (int c = 0; c < 8; c++) accf[j][c] = 0.f;

        for (int ab = 0; ab < 16; ab++) {
            __half2 acch[4][4];
#pragma unroll
            for (int j = 0; j < 4; j++)
#pragma unroll
                for (int i = 0; i < 4; i++) acch[j][i] = __float2half2_rn(0.f);

#pragma unroll
            for (int ai = 0; ai < 4; ai++) {
                int a = ab * 4 + ai;
                uint4 kku = *(uint4*)&s_kph[a * 136 + k0];
                uint2 qqu = *(uint2*)&s_qph[a * 72 + q0];
                __half2 w2s = s_w2s[a];
                const __half2* kk = (const __half2*)&kku;
                const __half*  qh = (const __half*)&qqu;
#pragma unroll
                for (int j = 0; j < 4; j++) {
                    __half2 qj = __half2half2(qh[j]);
#pragma unroll
                    for (int i = 0; i < 4; i++)
                        acch[j][i] = __hfma2(w2s, htanh2_fast(__hadd2(qj, kk[i])), acch[j][i]);
                }
            }
#pragma unroll
            for (int j = 0; j < 4; j++)
#pragma unroll
                for (int i = 0; i < 4; i++) {
                    float2 f = __half22float2(acch[j][i]);
                    accf[j][2 * i]     += f.x;
                    accf[j][2 * i + 1] += f.y;
                }
        }

        size_t base = ((size_t)(b * H_ + h) * QS_) * KS_ + kc * KC_;
#pragma unroll
        for (int j = 0; j < 4; j++)
#pragma unroll
            for (int i = 0; i < 4; i++) {
                float2 p = make_float2(accf[j][2 * i], accf[j][2 * i + 1]);
                *(float2*)&g_scores[base + (size_t)(q0 + j) * KS_ + k0 + 2 * i] = p;
            }
    }
}

// ================= kernel 2: softmax + p@V, 128-thr CTAs, 4/SM ==========
// CTA: 16 q x 64 d of one (b,h). 128 thr: tx(8)=d-group, tyq(2)=q-group(8q), kg(8)=k-group.
// smem (bytes):
//   s_p   f32[128][20] @0      10240   (transposed [k][q])
//   s_v   f32[128][68] @10240  34816
//   s_red f32[64][68]  @10240  17408   (ALIASED over s_v, used after main loop)
//   s_m   f32[16] @45056 ; s_inv f32[16] @45120  -> total 45184
#define SM2_BYTES 45184

__global__ void __launch_bounds__(128, 4) av_kernel(
    const float* __restrict__ x, const unsigned char* __restrict__ mask,
    float* __restrict__ out)
{
    extern __shared__ char sm2[];
    float* s_p   = (float*)sm2;
    float* s_v   = (float*)(sm2 + 10240);
    float* s_red = (float*)(sm2 + 10240);
    float* s_m   = (float*)(sm2 + 45056);
    float* s_inv = (float*)(sm2 + 45120);

    const int qq = blockIdx.x, h = blockIdx.y, b = blockIdx.z;
    const int tid = threadIdx.x, lane = tid & 31, warp = tid >> 5;
    const size_t sbase = (size_t)(b * H_ + h) * QS_ * KS_ + (size_t)qq * 16 * KS_;
    const float NEG_INF = __int_as_float(0xff800000);

    // ---- pass 1: row max + sum-exp (each of 4 warps: 4 of the 16 rows) ----
    {
        bool mk[16];
#pragma unroll
        for (int i = 0; i < 16; i++) mk[i] = (mask[b * KS_ + lane + 32 * i] != 0);
#pragma unroll
        for (int r = 0; r < 4; r++) {
            int ql = warp * 4 + r;
            float v[16], mx = NEG_INF;
#pragma unroll
            for (int i = 0; i < 16; i++) {
                float s = g_scores[sbase + (size_t)ql * KS_ + lane + 32 * i];
                if (mk[i]) s = NEG_INF;
                v[i] = s; mx = fmaxf(mx, s);
            }
#pragma unroll
            for (int o = 16; o; o >>= 1) mx = fmaxf(mx, __shfl_xor_sync(0xffffffffu, mx, o));
            float sum = 0.f;
#pragma unroll
            for (int i = 0; i < 16; i++) sum += __expf(v[i] - mx);
#pragma unroll
            for (int o = 16; o; o >>= 1) sum += __shfl_xor_sync(0xffffffffu, sum, o);
            if (lane == 0) { s_m[ql] = mx; s_inv[ql] = 1.f / sum; }
        }
    }
    __syncthreads();

    // ---- pass 2: chunked p @ V, 8q x 8d register tiles, 8-way k-split ----
    const int tx = tid & 7;            // d-group: d = 4tx and 32+4tx
    const int tyq = (tid >> 3) & 1;    // q0 = 8*tyq
    const int kg = tid >> 4;           // k-group of 16 within the chunk
    const int q0 = tyq * 8;

    ull acc2[8][4];
#pragma unroll
    for (int qi = 0; qi < 8; qi++)
#pragma unroll
        for (int c = 0; c < 4; c++) acc2[qi][c] = 0ULL;

    const int pq = tid & 15;           // q row this thread fills p for
    const int pkb = (tid >> 4) * 16;   // 16-k block this thread fills
    const float pm = s_m[pq], pinv = s_inv[pq];

    for (int cc = 0; cc < 4; cc++) {
        // p chunk: thread reads 16 consecutive k of row pq, stores transposed [k][q]
        {
            const float* gp = &g_scores[sbase + (size_t)pq * KS_ + cc * 128 + pkb];
            const unsigned char* mp = &mask[b * KS_ + cc * 128 + pkb];
#pragma unroll
            for (int j4 = 0; j4 < 4; j4++) {
                float4 s4 = *(const float4*)&gp[j4 * 4];
                s_p[(pkb + j4*4 + 0) * 20 + pq] = mp[j4*4+0] ? 0.f : __expf(s4.x - pm) * pinv;
                s_p[(pkb + j4*4 + 1) * 20 + pq] = mp[j4*4+1] ? 0.f : __expf(s4.y - pm) * pinv;
                s_p[(pkb + j4*4 + 2) * 20 + pq] = mp[j4*4+2] ? 0.f : __expf(s4.z - pm) * pinv;
                s_p[(pkb + j4*4 + 3) * 20 + pq] = mp[j4*4+3] ? 0.f : __expf(s4.w - pm) * pinv;
            }
        }
        // v chunk [128][64] : 128 thr x 16 float4
#pragma unroll
        for (int i = 0; i < 16; i++) {
            int idx = tid + 128 * i; int k = idx >> 4, d4 = idx & 15;
            *(float4*)&s_v[k * 68 + d4 * 4] =
                *(const float4*)&x[((size_t)b * KS_ + cc * 128 + k) * KD_ + h * DH_ + d4 * 4];
        }
        __syncthreads();

        // main: this thread's 16 k of the chunk
#pragma unroll 4
        for (int ki = 0; ki < 16; ki++) {
            int k = kg * 16 + ki;
            float4 va = *(float4*)&s_v[k * 68 + 4 * tx];
            float4 vb = *(float4*)&s_v[k * 68 + 32 + 4 * tx];
            ull v0 = pk2(va.x, va.y), v1 = pk2(va.z, va.w);
            ull v2 = pk2(vb.x, vb.y), v3 = pk2(vb.z, vb.w);
            float4 pa = *(float4*)&s_p[k * 20 + q0];
            float4 pb = *(float4*)&s_p[k * 20 + q0 + 4];
            float pr[8] = {pa.x, pa.y, pa.z, pa.w, pb.x, pb.y, pb.z, pb.w};
#pragma unroll
            for (int qi = 0; qi < 8; qi++) {
                ull p2r = pk2(pr[qi], pr[qi]);
                acc2[qi][0] = ffma2(p2r, v0, acc2[qi][0]);
                acc2[qi][1] = ffma2(p2r, v1, acc2[qi][1]);
                acc2[qi][2] = ffma2(p2r, v2, acc2[qi][2]);
                acc2[qi][3] = ffma2(p2r, v3, acc2[qi][3]);
            }
        }
        __syncthreads();
    }

    // ---- tree reduction over 8 k-groups (s_red aliases s_v) ----
    // round A: kg 4-7 store, kg 0-3 add
    if (kg >= 4) {
#pragma unroll
        for (int qi = 0; qi < 8; qi++) {
            int row = (kg - 4) * 16 + q0 + qi;
            float2 a0 = upk2(acc2[qi][0]), a1 = upk2(acc2[qi][1]);
            float2 a2v = upk2(acc2[qi][2]), a3 = upk2(acc2[qi][3]);
            *(float4*)&s_red[row * 68 + 4 * tx]      = make_float4(a0.x, a0.y, a1.x, a1.y);
            *(float4*)&s_red[row * 68 + 32 + 4 * tx] = make_float4(a2v.x, a2v.y, a3.x, a3.y);
        }
    }
    __syncthreads();
    if (kg < 4) {
#pragma unroll
        for (int qi = 0; qi < 8; qi++) {
            int row = kg * 16 + q0 + qi;
            float4 r0 = *(float4*)&s_red[row * 68 + 4 * tx];
            float4 r1 = *(float4*)&s_red[row * 68 + 32 + 4 * tx];
            acc2[qi][0] = fadd2(acc2[qi][0], pk2(r0.x, r0.y));
            acc2[qi][1] = fadd2(acc2[qi][1], pk2(r0.z, r0.w));
            acc2[qi][2] = fadd2(acc2[qi][2], pk2(r1.x, r1.y));
            acc2[qi][3] = fadd2(acc2[qi][3], pk2(r1.z, r1.w));
        }
    }
    __syncthreads();
    // round B: kg 2-3 store, kg 0-1 add
    if (kg == 2 || kg == 3) {
#pragma unroll
        for (int qi = 0; qi < 8; qi++) {
            int row = (kg - 2) * 16 + q0 + qi;
            float2 a0 = upk2(acc2[qi][0]), a1 = upk2(acc2[qi][1]);
            float2 a2v = upk2(acc2[qi][2]), a3 = upk2(acc2[qi][3]);
            *(float4*)&s_red[row * 68 + 4 * tx]      = make_float4(a0.x, a0.y, a1.x, a1.y);
            *(float4*)&s_red[row * 68 + 32 + 4 * tx] = make_float4(a2v.x, a2v.y, a3.x, a3.y);
        }
    }
    __syncthreads();
    if (kg < 2) {
#pragma unroll
        for (int qi = 0; qi < 8; qi++) {
            int row = kg * 16 + q0 + qi;
            float4 r0 = *(float4*)&s_red[row * 68 + 4 * tx];
            float4 r1 = *(float4*)&s_red[row * 68 + 32 + 4 * tx];
            acc2[qi][0] = fadd2(acc2[qi][0], pk2(r0.x, r0.y));
            acc2[qi][1] = fadd2(acc2[qi][1], pk2(r0.z, r0.w));
            acc2[qi][2] = fadd2(acc2[qi][2], pk2(r1.x, r1.y));
            acc2[qi][3] = fadd2(acc2[qi][3], pk2(r1.z, r1.w));
        }
    }
    __syncthreads();
    // round C: kg 1 stores, kg 0 adds + writes out
    if (kg == 1) {
#pragma unroll
        for (int qi = 0; qi < 8; qi++) {
            int row = q0 + qi;
            float2 a0 = upk2(acc2[qi][0]), a1 = upk2(acc2[qi][1]);
            float2 a2v = upk2(acc2[qi][2]), a3 = upk2(acc2[qi][3]);
            *(float4*)&s_red[row * 68 + 4 * tx]      = make_float4(a0.x, a0.y, a1.x, a1.y);
            *(float4*)&s_red[row * 68 + 32 + 4 * tx] = make_float4(a2v.x, a2v.y, a3.x, a3.y);
        }
    }
    __syncthreads();
    if (kg == 0) {
#pragma unroll
        for (int qi = 0; qi < 8; qi++) {
            int row = q0 + qi;
            float4 r0 = *(float4*)&s_red[row * 68 + 4 * tx];
            float4 r1 = *(float4*)&s_red[row * 68 + 32 + 4 * tx];
            float2 a0 = upk2(fadd2(acc2[qi][0], pk2(r0.x, r0.y)));
            float2 a1 = upk2(fadd2(acc2[qi][1], pk2(r0.z, r0.w)));
            float2 a2v = upk2(fadd2(acc2[qi][2], pk2(r1.x, r1.y)));
            float2 a3 = upk2(fadd2(acc2[qi][3], pk2(r1.z, r1.w)));
            size_t ob = ((size_t)(b * QS_ + qq * 16 + q0 + qi)) * QD_ + h * DH_;
            *(float4*)&out[ob + 4 * tx]      = make_float4(a0.x, a0.y, a1.x, a1.y);
            *(float4*)&out[ob + 32 + 4 * tx] = make_float4(a2v.x, a2v.y, a3.x, a3.y);
        }
    }
}

// ---------------- launch ----------------
extern "C" void kernel_launch(void* const* d_in, const int* in_sizes, int n_in,
                              void* d_out, int out_size) {
    const float* x     = (const float*)d_in[0];
    const float* query = (const float*)d_in[1];
    const float* W     = (const float*)d_in[2];
    const float* bias  = (const float*)d_in[3];
    const float* w2    = (const float*)d_in[4];
    const unsigned char* mask = (const unsigned char*)d_in[5];
    float* out = (float*)d_out;

    cudaFuncSetAttribute(scores_kernel, cudaFuncAttributeMaxDynamicSharedMemorySize, SM1_BYTES);
    cudaFuncSetAttribute(av_kernel,     cudaFuncAttributeMaxDynamicSharedMemorySize, SM2_BYTES);

    scores_kernel<<<dim3(KS_ / KC_, H_, B_), 256, SM1_BYTES>>>(x, query, W, bias, w2);
    av_kernel<<<dim3(4, H_, B_), 128, SM2_BYTES>>>(x, mask, out);
}

// round 5
// speedup vs baseline: 1.4825x; 1.1804x over previous
#include <cuda_runtime.h>

#define B_  8
#define H_  8
#define QS_ 64
#define KS_ 512
#define A_  64
#define DH_ 64
#define KC_ 128
#define NC_ 4
#define QD_ 512
#define KD_ 512

typedef unsigned long long ull;

// scratch: per-chunk partial outputs + softmax stats
__device__ float g_pout[B_*H_*NC_*QS_*DH_];   // 4 MB
__device__ float g_Mx[B_*H_*NC_*QS_];
__device__ float g_Sx[B_*H_*NC_*QS_];

__device__ __forceinline__ float fast_tanh(float v) {
    float y; asm("tanh.approx.f32 %0, %1;" : "=f"(y) : "f"(v)); return y;
}
__device__ __forceinline__ ull pk2(float x, float y) {
    ull r; asm("mov.b64 %0, {%1, %2};" : "=l"(r) : "f"(x), "f"(y)); return r;
}
__device__ __forceinline__ float2 upk2(ull v) {
    float2 r; asm("mov.b64 {%0, %1}, %2;" : "=f"(r.x), "=f"(r.y) : "l"(v)); return r;
}
__device__ __forceinline__ ull ffma2(ull a, ull b, ull c) {
    ull d; asm("fma.rn.f32x2 %0, %1, %2, %3;" : "=l"(d) : "l"(a), "l"(b), "l"(c)); return d;
}

// ---------------- smem layout (bytes) ----------------
// A: 0      s_xv   f32[128][68] 34816    (x chunk == V, persists)
// B: 34816  phase1: query[64][64] (16384) + Wq @+16384 [64][68] (17408)
//           phase2+: s_kp f32[64][132] (33792)
// C: 68608  phase2: s_Wk [64][68] (17408); phase4+: s_p f32[64][132] (33792, spans C+D)
// D: 86016  s_qp f32[64][68] (17408)  (written ph1, read ph3, clobbered by p in ph4)
// E: 103424 s_bias f32[64]; 103680 s_w2 f32[64]
#define SMF_BYTES 103936

__global__ void __launch_bounds__(256, 2) fused_kernel(
    const float* __restrict__ x, const float* __restrict__ query,
    const float* __restrict__ W, const float* __restrict__ bias,
    const float* __restrict__ w2, const unsigned char* __restrict__ mask)
{
    extern __shared__ char sm[];
    float* s_xv  = (float*)(sm);
    float* s_q   = (float*)(sm + 34816);
    float* s_W1  = (float*)(sm + 51200);
    float* s_kp  = (float*)(sm + 34816);
    float* s_Wk  = (float*)(sm + 68608);
    float* s_p   = (float*)(sm + 68608);
    float* s_qp  = (float*)(sm + 86016);
    float* s_bias= (float*)(sm + 103424);
    float* s_w2  = (float*)(sm + 103680);

    const int kc = blockIdx.x, h = blockIdx.y, b = blockIdx.z;
    const int tid = threadIdx.x;
    const int tx = tid & 15, ty = tid >> 4;
    const int bh = b * H_ + h;
    const float NEG_INF = __int_as_float(0xff800000);

    if (tid < 64) { s_bias[tid] = bias[tid]; s_w2[tid] = w2[tid]; }

    // ---- phase 1: stage query [64][64] + Wq [64][68] ----
#pragma unroll
    for (int i = 0; i < 4; i++) {
        int idx = tid + 256 * i; int q = idx >> 4, d4 = idx & 15;
        *(float4*)&s_q[q * 64 + d4 * 4] =
            *(const float4*)&query[(size_t)(b * QS_ + q) * QD_ + h * DH_ + d4 * 4];
    }
#pragma unroll
    for (int i = 0; i < 4; i++) {
        int idx = tid + 256 * i; int a = idx >> 4, d4 = idx & 15;
        *(float4*)&s_W1[a * 68 + d4 * 4] = *(const float4*)&W[a * 128 + 64 + d4 * 4];
    }
    __syncthreads();

    // ---- qp GEMM (f32x2): q rows ty*4+i, a cols tx+16j -> s_qp[a][q] ----
    {
        ull acc2[4][4];
#pragma unroll
        for (int i = 0; i < 4; i++)
#pragma unroll
            for (int j = 0; j < 4; j++) acc2[i][j] = 0ULL;
#pragma unroll
        for (int d4 = 0; d4 < 16; d4++) {
            ull qv[4][2], wv[4][2];
#pragma unroll
            for (int i = 0; i < 4; i++) {
                float4 v = *(float4*)&s_q[(ty * 4 + i) * 64 + d4 * 4];
                qv[i][0] = pk2(v.x, v.y); qv[i][1] = pk2(v.z, v.w);
            }
#pragma unroll
            for (int j = 0; j < 4; j++) {
                float4 v = *(float4*)&s_W1[(tx + 16 * j) * 68 + d4 * 4];
                wv[j][0] = pk2(v.x, v.y); wv[j][1] = pk2(v.z, v.w);
            }
#pragma unroll
            for (int i = 0; i < 4; i++)
#pragma unroll
                for (int j = 0; j < 4; j++) {
                    acc2[i][j] = ffma2(qv[i][0], wv[j][0], acc2[i][j]);
                    acc2[i][j] = ffma2(qv[i][1], wv[j][1], acc2[i][j]);
                }
        }
#pragma unroll
        for (int i = 0; i < 4; i++)
#pragma unroll
            for (int j = 0; j < 4; j++) {
                float2 p = upk2(acc2[i][j]);
                s_qp[(tx + 16 * j) * 68 + ty * 4 + i] = p.x + p.y + s_bias[tx + 16 * j];
            }
    }
    __syncthreads();

    // ---- phase 2: stage x chunk [128][68] + Wk ----
#pragma unroll
    for (int i = 0; i < 8; i++) {
        int idx = tid + 256 * i; int k = idx >> 4, d4 = idx & 15;
        *(float4*)&s_xv[k * 68 + d4 * 4] =
            *(const float4*)&x[((size_t)b * KS_ + kc * KC_ + k) * KD_ + h * DH_ + d4 * 4];
    }
#pragma unroll
    for (int i = 0; i < 4; i++) {
        int idx = tid + 256 * i; int a = idx >> 4, d4 = idx & 15;
        *(float4*)&s_Wk[a * 68 + d4 * 4] = *(const float4*)&W[a * 128 + d4 * 4];
    }
    __syncthreads();

    // ---- kp GEMM (f32x2): k rows ty*8+i, a cols tx+16j -> s_kp[a][k] ----
    {
        ull acc2[8][4];
#pragma unroll
        for (int i = 0; i < 8; i++)
#pragma unroll
            for (int j = 0; j < 4; j++) acc2[i][j] = 0ULL;
#pragma unroll
        for (int d4 = 0; d4 < 16; d4++) {
            ull kv[8][2], wv[4][2];
#pragma unroll
            for (int i = 0; i < 8; i++) {
                float4 v = *(float4*)&s_xv[(ty * 8 + i) * 68 + d4 * 4];
                kv[i][0] = pk2(v.x, v.y); kv[i][1] = pk2(v.z, v.w);
            }
#pragma unroll
            for (int j = 0; j < 4; j++) {
                float4 v = *(float4*)&s_Wk[(tx + 16 * j) * 68 + d4 * 4];
                wv[j][0] = pk2(v.x, v.y); wv[j][1] = pk2(v.z, v.w);
            }
#pragma unroll
            for (int i = 0; i < 8; i++)
#pragma unroll
                for (int j = 0; j < 4; j++) {
                    acc2[i][j] = ffma2(kv[i][0], wv[j][0], acc2[i][j]);
                    acc2[i][j] = ffma2(kv[i][1], wv[j][1], acc2[i][j]);
                }
        }
#pragma unroll
        for (int i = 0; i < 8; i++)
#pragma unroll
            for (int j = 0; j < 4; j++) {
                float2 p = upk2(acc2[i][j]);
                s_kp[(tx + 16 * j) * 132 + ty * 8 + i] = p.x + p.y;
            }
    }
    __syncthreads();

    // ---- phase 3: scores[q][k] = sum_a w2[a]*tanh(qp[q][a] + kp[k][a]) ----
    const int q0 = ty * 4, k0 = tx * 8;
    float acc[4][8];
#pragma unroll
    for (int j = 0; j < 4; j++)
#pragma unroll
        for (int i = 0; i < 8; i++) acc[j][i] = 0.f;

#pragma unroll 4
    for (int a = 0; a < A_; a++) {
        float w2a = s_w2[a];
        float4 qv = *(float4*)&s_qp[a * 68 + q0];
        float4 k0v = *(float4*)&s_kp[a * 132 + k0];
        float4 k1v = *(float4*)&s_kp[a * 132 + k0 + 4];
        float qs[4] = {qv.x, qv.y, qv.z, qv.w};
        float kv[8] = {k0v.x, k0v.y, k0v.z, k0v.w, k1v.x, k1v.y, k1v.z, k1v.w};
#pragma unroll
        for (int j = 0; j < 4; j++)
#pragma unroll
            for (int i = 0; i < 8; i++)
                acc[j][i] += w2a * fast_tanh(qs[j] + kv[i]);
    }

    // ---- phase 4: chunk softmax stats (registers + half-warp shuffles) ----
    unsigned char mk[8];
    {
        const unsigned char* mrow = &mask[b * KS_ + kc * KC_ + k0];
#pragma unroll
        for (int i = 0; i < 8; i++) mk[i] = mrow[i];
    }
    float rowmax[4], rowsum[4];
#pragma unroll
    for (int j = 0; j < 4; j++) {
        float mx = NEG_INF;
#pragma unroll
        for (int i = 0; i < 8; i++) {
            if (mk[i]) acc[j][i] = NEG_INF;
            mx = fmaxf(mx, acc[j][i]);
        }
#pragma unroll
        for (int o = 8; o; o >>= 1) mx = fmaxf(mx, __shfl_xor_sync(0xffffffffu, mx, o));
        float s = 0.f;
#pragma unroll
        for (int i = 0; i < 8; i++) {
            float p = mk[i] ? 0.f : __expf(acc[j][i] - mx);
            acc[j][i] = p;
            s += p;
        }
#pragma unroll
        for (int o = 8; o; o >>= 1) s += __shfl_xor_sync(0xffffffffu, s, o);
        rowmax[j] = mx; rowsum[j] = s;
    }
    __syncthreads();   // all phase-3 smem reads done before p overwrites qp region

    // write p (unnormalized) to s_p[q][k]
#pragma unroll
    for (int j = 0; j < 4; j++) {
        *(float4*)&s_p[(q0 + j) * 132 + k0]     = make_float4(acc[j][0], acc[j][1], acc[j][2], acc[j][3]);
        *(float4*)&s_p[(q0 + j) * 132 + k0 + 4] = make_float4(acc[j][4], acc[j][5], acc[j][6], acc[j][7]);
    }
    if (tx == 0) {
#pragma unroll
        for (int j = 0; j < 4; j++) {
            g_Mx[(bh * NC_ + kc) * QS_ + q0 + j] = rowmax[j];
            g_Sx[(bh * NC_ + kc) * QS_ + q0 + j] = rowsum[j];
        }
    }
    __syncthreads();

    // ---- phase 5: partial out = p @ V  (4q x 4d per thread) ----
    {
        const int txd = tid & 15, tyq = tid >> 4;
        const int d0 = txd * 4, q0b = tyq * 4;
        ull o2[4][2];
#pragma unroll
        for (int j = 0; j < 4; j++) { o2[j][0] = 0ULL; o2[j][1] = 0ULL; }

#pragma unroll 4
        for (int k = 0; k < KC_; k++) {
            float4 v = *(float4*)&s_xv[k * 68 + d0];
            ull v0 = pk2(v.x, v.y), v1 = pk2(v.z, v.w);
#pragma unroll
            for (int j = 0; j < 4; j++) {
                float p = s_p[(q0b + j) * 132 + k];
                ull p2 = pk2(p, p);
                o2[j][0] = ffma2(p2, v0, o2[j][0]);
                o2[j][1] = ffma2(p2, v1, o2[j][1]);
            }
        }
#pragma unroll
        for (int j = 0; j < 4; j++) {
            float2 a0 = upk2(o2[j][0]), a1 = upk2(o2[j][1]);
            *(float4*)&g_pout[(size_t)((bh * NC_ + kc) * QS_ + q0b + j) * DH_ + d0] =
                make_float4(a0.x, a0.y, a1.x, a1.y);
        }
    }
}

// ---------------- combine: merge 4 chunk partials per (b,h) ----------------
__global__ void __launch_bounds__(128) combine_kernel(float* __restrict__ out)
{
    const int qq = blockIdx.x, bh = blockIdx.y;
    const int tid = threadIdx.x;
    const int qr = tid >> 3, dg = tid & 7;
    const int q = qq * 16 + qr;
    const int b = bh >> 3, h = bh & 7;
    const int d0 = dg * 8;
    const float NEG_INF = __int_as_float(0xff800000);

    float Mc[NC_], Sc[NC_];
    float M = NEG_INF;
#pragma unroll
    for (int c = 0; c < NC_; c++) {
        Mc[c] = g_Mx[(bh * NC_ + c) * QS_ + q];
        Sc[c] = g_Sx[(bh * NC_ + c) * QS_ + q];
        M = fmaxf(M, Mc[c]);
    }
    float w[NC_], denom = 0.f;
#pragma unroll
    for (int c = 0; c < NC_; c++) {
        w[c] = __expf(Mc[c] - M);
        denom += w[c] * Sc[c];
    }
    float inv = 1.f / denom;

    float4 a0 = make_float4(0.f, 0.f, 0.f, 0.f);
    float4 a1 = make_float4(0.f, 0.f, 0.f, 0.f);
#pragma unroll
    for (int c = 0; c < NC_; c++) {
        const float* p = &g_pout[(size_t)((bh * NC_ + c) * QS_ + q) * DH_ + d0];
        float4 v0 = *(const float4*)&p[0];
        float4 v1 = *(const float4*)&p[4];
        a0.x += w[c] * v0.x; a0.y += w[c] * v0.y; a0.z += w[c] * v0.z; a0.w += w[c] * v0.w;
        a1.x += w[c] * v1.x; a1.y += w[c] * v1.y; a1.z += w[c] * v1.z; a1.w += w[c] * v1.w;
    }
    a0.x *= inv; a0.y *= inv; a0.z *= inv; a0.w *= inv;
    a1.x *= inv; a1.y *= inv; a1.z *= inv; a1.w *= inv;

    size_t ob = (size_t)(b * QS_ + q) * QD_ + h * DH_ + d0;
    *(float4*)&out[ob]     = a0;
    *(float4*)&out[ob + 4] = a1;
}

// ---------------- launch ----------------
extern "C" void kernel_launch(void* const* d_in, const int* in_sizes, int n_in,
                              void* d_out, int out_size) {
    const float* x     = (const float*)d_in[0];
    const float* query = (const float*)d_in[1];
    const float* W     = (const float*)d_in[2];
    const float* bias  = (const float*)d_in[3];
    const float* w2    = (const float*)d_in[4];
    const unsigned char* mask = (const unsigned char*)d_in[5];
    float* out = (float*)d_out;

    cudaFuncSetAttribute(fused_kernel, cudaFuncAttributeMaxDynamicSharedMemorySize, SMF_BYTES);

    fused_kernel<<<dim3(NC_, H_, B_), 256, SMF_BYTES>>>(x, query, W, bias, w2, mask);
    combine_kernel<<<dim3(4, B_ * H_), 128>>>(out);
}